// round 9
// baseline (speedup 1.0000x reference)
#include <cuda_runtime.h>
#include <cstdint>

#define NPOS   1296
#define NPOSX  36
#define BCN    32
#define HW     160
#define SLOT   52                       // floats per (pos,n) record: 49 den + coord + pad
#define STEPS  (NPOS*10)                // 12960 updates per plane (chronological)
#define NB32   (STEPS/32)               // 405 coord blocks
#define ROWSTR 164
#define PLANE_ELEMS (160*ROWSTR)
#define SMEM_C_BYTES (2*PLANE_ELEMS*4)  // 209,920 B

__device__ float g_den[(size_t)BCN*NPOS*10*SLOT + 4096];   // den + packed coords (+pad for prefetch overrun)
__device__ float g_M[49*49];
__device__ float g_b2[10*49];

// ---------------- Kernel P: fuse the two linear layers ----------------
__global__ void __launch_bounds__(256) kprep(const float* __restrict__ Wp, const float* __restrict__ bp,
                      const float* __restrict__ pe, const float* __restrict__ Wb,
                      const float* __restrict__ bb) {
    int t = blockIdx.x * blockDim.x + threadIdx.x;
    int stride = gridDim.x * blockDim.x;
    for (int idx = t; idx < 49*49; idx += stride) {
        int k = idx/49, j = idx%49;
        float a = 0.f;
        for (int e = 0; e < 128; e++) a = fmaf(Wp[k*128+e], Wb[e*49+j], a);
        g_M[idx] = a;
    }
    for (int idx = t; idx < 10*49; idx += stride) {
        int n = idx/49, j = idx%49;
        float a = bb[j];
        for (int e = 0; e < 128; e++) a = fmaf(bp[e] + pe[n*128+e], Wb[e*49+j], a);
        g_b2[idx] = a;
    }
}

// ---------------- Kernel A: sim + exact top-10 + fused projection ----------------
// One block = one position x 8 bc-planes: Ms staged ONCE per block (8x less L2 traffic).
__global__ void __launch_bounds__(256, 6) kmain(const float* __restrict__ images) {
    __shared__ float win[400];
    __shared__ float ref[49];
    __shared__ float Ms[49*49];
    __shared__ float b2s[10*49];
    __shared__ unsigned long long keys[224];
    __shared__ unsigned widx[10];

    int t   = threadIdx.x;
    int blk = blockIdx.x;
    int p   = blk >> 2;          // position (x-outer, y-inner)
    int oct = blk & 3;           // bc octet
    int xidx = p / NPOSX, yidx = p % NPOSX;
    int x = 4*xidx, y = 4*yidx;
    int xb0 = max(x-7, 0), yb0 = max(y-7, 0);
    int jmax = (x + 13 - xb0) - 7;     // col-offset validity (winW - P)
    int imax = (y + 13 - yb0) - 7;     // row-offset validity (winH - P)

    // stage fused matrix + bias once per block
    for (int i = t; i < 49*49; i += 256) Ms[i] = g_M[i];
    for (int i = t; i < 490;   i += 256) b2s[i] = g_b2[i];

    int lane = t & 31, wid = t >> 5;

    for (int g = 0; g < 8; g++) {
        int bc = oct*8 + g;
        const float* ip = images + (size_t)bc*HW*HW;
        __syncthreads();                      // win free (covers Ms staging on g=0)
        for (int idx = t; idx < 400; idx += 256)
            win[idx] = ip[(yb0 + idx/20)*HW + xb0 + idx%20];
        if (t < 49)  ref[t] = ip[(y + t/7)*HW + x + t%7];
        __syncthreads();

        // sim[i][j]; composite key = (orderable value, smaller-index-wins)
        unsigned long long key = 0ull;
        if (t < 196) {
            int i = t/14, j = t%14;
            if (i <= imax && j <= jmax) {
                float s = 0.f;
                #pragma unroll
                for (int u = 0; u < 7; u++)
                    #pragma unroll
                    for (int v = 0; v < 7; v++)
                        s = fmaf(win[(i+u)*20 + j+v], ref[u*7+v], s);
                unsigned b   = __float_as_uint(s);
                unsigned ord = (b & 0x80000000u) ? ~b : (b | 0x80000000u);
                key = ((unsigned long long)ord << 32) | (unsigned)(1023 - t);
            }
        }
        if (t < 224) keys[t] = key;
        __syncthreads();

        if (wid == 0) {
            // single-warp exact top-10 over 224 keys
            unsigned long long kk[7];
            #pragma unroll
            for (int s = 0; s < 7; s++) kk[s] = keys[lane + 32*s];
            #pragma unroll
            for (int r = 0; r < 10; r++) {
                unsigned long long m = kk[0];
                #pragma unroll
                for (int s = 1; s < 7; s++) if (kk[s] > m) m = kk[s];
                #pragma unroll
                for (int off = 16; off; off >>= 1) {
                    unsigned long long o = __shfl_xor_sync(0xFFFFFFFFu, m, off);
                    if (o > m) m = o;
                }
                if (lane == 0) widx[r] = 1023u - (unsigned)(m & 0xFFFFFFFFull);
                #pragma unroll
                for (int s = 0; s < 7; s++) if (kk[s] == m) kk[s] = 0ull;
            }
        }
        __syncthreads();

        // den[n][j] = b2[n][j] + sum_k patch[k]*M[k][j], patch transposed from win
        size_t base0 = (((size_t)bc*NPOS + p)*10)*SLOT;
        #pragma unroll
        for (int base = 0; base < 490; base += 256) {
            int tt = base + t;
            if (tt < 490) {
                int n = tt/49, j = tt%49;
                unsigned w = widx[n];
                int oy = w/14, ox = w%14;
                float acc = b2s[n*49 + j];
                #pragma unroll
                for (int kc = 0; kc < 7; kc++)
                    #pragma unroll
                    for (int kr = 0; kr < 7; kr++)
                        acc = fmaf(win[(oy+kr)*20 + ox+kc], Ms[(kc*7+kr)*49 + j], acc);
                g_den[base0 + n*SLOT + j] = acc;
            }
        }
        if (t < 10) {
            unsigned w = widx[t];
            int oy = w/14, ox = w%14;
            unsigned xi = (unsigned)(oy + xb0);   // source's coordinate swap kept
            unsigned yi = (unsigned)(ox + yb0);
            ((unsigned*)g_den)[base0 + t*SLOT + 49] = xi | (yi << 8);
        }
    }
}

// ---------------- Kernel C: scatter, 8 row-stripe warps per plane, no inter-warp sync ----------------
__device__ __forceinline__ void pref8(unsigned vec, int baseidx, int gstep,
        const float* __restrict__ denp, int lane, int k2, bool val2,
        int q1, int q2, int lo, float* D1, float* D2) {
    #pragma unroll
    for (int q = 0; q < 8; q++) {
        unsigned c_ = __shfl_sync(0xFFFFFFFFu, vec, baseidx + q);
        int yi_ = (int)((c_ >> 8) & 255u);
        bool o1 = ((unsigned)(yi_ + q1 - lo) <= 19u);
        bool o2 = val2 && ((unsigned)(yi_ + q2 - lo) <= 19u);
        const float* pp = denp + (size_t)(gstep + q) * SLOT;
        D1[q] = o1 ? __ldg(pp + lane) : 0.f;
        D2[q] = o2 ? __ldg(pp + k2)   : 0.f;
    }
}

__global__ void __launch_bounds__(256) kscatter(const float* __restrict__ images,
                                                float* __restrict__ out) {
    extern __shared__ float sm[];
    float* img = sm;
    float* cnt = sm + PLANE_ELEMS;
    volatile float* vimg = img;
    volatile float* vcnt = cnt;

    int plane = blockIdx.x;
    int tid = threadIdx.x, lane = tid & 31, w = tid >> 5;
    int lo = w * 20;                       // owned rows [lo, lo+19]
    const float*    denp = g_den + (size_t)plane * ((size_t)STEPS*SLOT);
    const unsigned* denu = (const unsigned*)denp;

    const float* src = images + (size_t)plane*HW*HW;
    for (int i = tid; i < HW*HW; i += 256) {
        img[(i/HW)*ROWSTR + (i%HW)] = src[i];
        cnt[(i/HW)*ROWSTR + (i%HW)] = 1.0f;
    }
    __syncthreads();

    int q1 = lane / 7, m1 = lane % 7;      // element k1 = lane
    int k2 = lane + 32;
    bool val2 = (k2 < 49);                 // element k2 (lanes 0..16 only)
    int q2 = val2 ? k2/7 : 0, m2 = val2 ? k2%7 : 0;

    float d1b[2][8], d2b[2][8];

    unsigned co_cur = denu[(size_t)lane*SLOT + 49];        // coords of steps 0..31
    pref8(co_cur, 0, 0, denp, lane, k2, val2, q1, q2, lo, d1b[0], d2b[0]);

    for (int b = 0; b < NB32; b++) {
        int nb = (b+1 < NB32) ? (b+1) : (NB32-1);
        unsigned co_nxt = denu[((size_t)(nb*32 + lane))*SLOT + 49];
        int stepbase = b*32;
        #pragma unroll
        for (int sub = 0; sub < 4; sub++) {
            int pb = sub & 1;              // buffer holding current 8 steps
            // prefetch next 8 steps into the other buffer
            unsigned pvec = (sub < 3) ? co_cur : co_nxt;
            pref8(pvec, ((sub+1)*8) & 31, stepbase + (sub+1)*8,
                  denp, lane, k2, val2, q1, q2, lo, d1b[pb^1], d2b[pb^1]);
            // process current 8 steps
            #pragma unroll
            for (int q = 0; q < 8; q++) {
                unsigned c_ = __shfl_sync(0xFFFFFFFFu, co_cur, sub*8 + q);
                int xi = (int)(c_ & 255u), yi = (int)((c_ >> 8) & 255u);
                int rr1 = yi + q1, ir1 = xi + q1;
                int rr2 = yi + q2, ir2 = xi + q2;
                bool o1  = ((unsigned)(rr1 - lo) <= 19u);
                bool oi1 = ((unsigned)(ir1 - lo) <= 19u);
                bool o2  = val2 && ((unsigned)(rr2 - lo) <= 19u);
                bool oi2 = val2 && ((unsigned)(ir2 - lo) <= 19u);
                if (!__ballot_sync(0xFFFFFFFFu, o1 | oi1 | o2 | oi2)) continue;
                int a1  = rr1*ROWSTR + xi + m1;            // img/cnt-read cell (k1)
                int a2  = rr2*ROWSTR + xi + m2;
                int i1  = ir1*ROWSTR + yi + m1;            // cnt-increment cell (transposed)
                int i2  = ir2*ROWSTR + yi + m2;
                float c1 = 1.f, v1 = 0.f, c2 = 1.f, v2 = 0.f, t1 = 0.f, t2 = 0.f;
                if (o1)  { c1 = vcnt[a1]; v1 = vimg[a1]; }
                if (o2)  { c2 = vcnt[a2]; v2 = vimg[a2]; }
                if (oi1) { t1 = vcnt[i1]; }
                if (oi2) { t2 = vcnt[i2]; }
                float r1 = __fdividef(fmaf(v1, c1, d1b[pb][q]), c1 + 1.0f);
                float r2 = __fdividef(fmaf(v2, c2, d2b[pb][q]), c2 + 1.0f);
                if (o1)  vimg[a1] = r1;
                if (o2)  vimg[a2] = r2;
                if (oi1) vcnt[i1] = t1 + 1.0f;
                if (oi2) vcnt[i2] = t2 + 1.0f;
            }
        }
        co_cur = co_nxt;
    }
    __syncthreads();

    float* op = out + (size_t)plane*HW*HW;
    for (int i = tid; i < HW*HW; i += 256)
        op[i] = img[(i/HW)*ROWSTR + (i%HW)];
}

extern "C" void kernel_launch(void* const* d_in, const int* in_sizes, int n_in,
                              void* d_out, int out_size) {
    const float* images = (const float*)d_in[0];
    const float* Wp     = (const float*)d_in[1];
    const float* bp     = (const float*)d_in[2];
    const float* pe     = (const float*)d_in[3];
    const float* Wb     = (const float*)d_in[4];
    const float* bb     = (const float*)d_in[5];
    float* out = (float*)d_out;

    cudaFuncSetAttribute(kscatter, cudaFuncAttributeMaxDynamicSharedMemorySize, SMEM_C_BYTES);

    kprep<<<12, 256>>>(Wp, bp, pe, Wb, bb);
    kmain<<<NPOS*4, 256>>>(images);
    kscatter<<<BCN, 256, SMEM_C_BYTES>>>(images, out);
}